// round 13
// baseline (speedup 1.0000x reference)
#include <cuda_runtime.h>
#include <cuda_bf16.h>
#include <math.h>
#include <stdint.h>

// Problem constants
#define CIN   256
#define COUT  128
#define Hh    64
#define Ww    192
#define HW    (Hh*Ww)          // 12288
#define Hp    (Hh+2)           // 66
#define Wp    (Ww+2)           // 194
#define Pp    (Hp*Wp)          // 12804
#define EPSv  1e-5f
#define LEAK  0.01f

// ---------------- scratch (static __device__ — no allocation) ----------------
__device__ float4 g_tap[HW * 9];            // packed {base(int), w0, w1, w2} per (px,tap)
__device__ float g_xT[HW * CIN];            // x transposed to [p][c]  (12.6 MB)
__device__ float g_rot[9 * 256];            // ro transposed to [k][c]
__device__ __nv_bfloat16 g_y0h[HW * CIN];   // gather out, PIXEL-major [p][c], hi
__device__ __nv_bfloat16 g_y0l[HW * CIN];   // lo
__device__ float g_t1[COUT * HW];           // GEMM fp32 outputs [c][p]
__device__ float g_t3[COUT * HW];
__device__ __nv_bfloat16 g_t2h[COUT * HW];  // dw output hi/lo planes [c][p]
__device__ __nv_bfloat16 g_t2l[COUT * HW];
__device__ __nv_bfloat16 g_wh[COUT * (CIN + COUT + COUT)];  // pre-split weights hi
__device__ __nv_bfloat16 g_wl[COUT * (CIN + COUT + COUT)];  // lo
__device__ float g_sum[3][COUT];
__device__ float g_sum2[3][COUT];

__device__ __forceinline__ void split_bf16(float v, __nv_bfloat16& h, __nv_bfloat16& l) {
    h = __float2bfloat16(v);
    l = __float2bfloat16(v - __bfloat162float(h));
}

// =================== 1) fused prep kernel ===================
// blocks [0,768)       : x transpose, 64px x 64ch float4 tiles
// blocks [768,816)     : gather tables (48 blocks x 256 px)
// blocks [816,1072)    : weight split (256 blocks x 256 elems)
// block  1072          : stat zero + ro transpose
__global__ void __launch_bounds__(256)
prep_kernel(const float* __restrict__ x, const float* __restrict__ xr,
            const float* __restrict__ ro,
            const float* __restrict__ w0, const float* __restrict__ w1,
            const float* __restrict__ w2) {
    int bid = blockIdx.x;
    int tid = threadIdx.x;

    if (bid < 768) {
        __shared__ float tile[64][65];
        int pb = (bid % 192) * 64, cb = (bid / 192) * 64;
        int tx = tid & 15, ty = tid >> 4;
        #pragma unroll
        for (int j = 0; j < 4; j++) {
            int cl = ty + 16 * j;
            float4 v = *(const float4*)&x[(size_t)(cb + cl) * HW + pb + tx * 4];
            tile[cl][tx * 4 + 0] = v.x;
            tile[cl][tx * 4 + 1] = v.y;
            tile[cl][tx * 4 + 2] = v.z;
            tile[cl][tx * 4 + 3] = v.w;
        }
        __syncthreads();
        #pragma unroll
        for (int j = 0; j < 4; j++) {
            int pl = ty + 16 * j;
            int cl = tx * 4;
            float4 v = make_float4(tile[cl][pl], tile[cl + 1][pl],
                                   tile[cl + 2][pl], tile[cl + 3][pl]);
            *(float4*)&g_xT[(size_t)(pb + pl) * 256 + cb + cl] = v;
        }
        return;
    }

    if (bid < 816) {
        int p = (bid - 768) * 256 + tid;
        if (p >= HW) return;
        float off = 3.0f * (1.0f / (1.0f + expf(-xr[p])));
        int r = p / Ww, cc = p - r * Ww;
        float v0 = (float)((r + 1) * Wp + (cc + 1));
        const float xo9[9] = {-1,0,1,-1,0,1,-1,0,1};
        const float yo9[9] = {-1,-1,-1,0,0,0,1,1,1};
        const float Pm1 = (float)(Pp - 1);
        const float Wpf = (float)Wp;
        #pragma unroll
        for (int k = 0; k < 9; k++) {
            float xo = xo9[k], yo = yo9[k];
            float pre  = v0 + xo + yo * Wpf;
            float offv = __fadd_rn(__fmul_rn(off, xo), yo * Wpf);
            float after = __fadd_rn(pre, offv);
            float avf  = fminf(fmaxf(pre + floorf(offv), 0.f), Pm1);
            float avf1 = fminf(fmaxf(avf + xo, 0.f), Pm1);
            float avc  = fminf(fmaxf(pre + ceilf(offv), 0.f), Pm1);
            float avc1 = fminf(fmaxf(avc + xo, 0.f), Pm1);
            float g1w = fabsf((after - avf)  / Wpf);
            float g2w = fabsf((avc1 - after) / Wpf);
            float wq[4];
            wq[0] = g1w * fabsf(after - avf);
            wq[1] = g1w * fabsf(avf1 - after);
            wq[2] = g2w * fabsf(after - avc1);
            wq[3] = g2w * fabsf(avc  - after);
            int iq[4] = {(int)avf, (int)avf1, (int)avc1, (int)avc};
            int lo = min(min(iq[0], iq[1]), min(iq[2], iq[3]));
            float w3[3] = {0.f, 0.f, 0.f};
            #pragma unroll
            for (int j = 0; j < 4; j++) w3[iq[j] - lo] += wq[j];
            int vbase = -1, firstslot = 0;
            #pragma unroll
            for (int s = 0; s < 3; s++) {
                int id = lo + s;
                int rr = id / Wp, c2 = id - rr * Wp;
                bool valid = (rr >= 1 && rr <= Hh && c2 >= 1 && c2 <= Ww);
                if (!valid) w3[s] = 0.f;
                else if (w3[s] != 0.f && vbase < 0) {
                    vbase = (rr - 1) * Ww + (c2 - 1);
                    firstslot = s;
                }
            }
            float fw[3] = {0.f, 0.f, 0.f};
            int bidx = 0;
            if (vbase >= 0) {
                int base = vbase - firstslot;
                bidx = min(max(base, 0), HW - 3);
                #pragma unroll
                for (int s = 0; s < 3; s++)
                    if (w3[s] != 0.f) fw[(base + s) - bidx] += w3[s];
            }
            g_tap[p * 9 + k] = make_float4(__int_as_float(bidx), fw[0], fw[1], fw[2]);
        }
        return;
    }

    if (bid < 1072) {
        int i = (bid - 816) * 256 + tid;
        const int n0 = COUT * CIN;
        const int n1 = COUT * COUT;
        float v;
        if (i < n0)                 v = w0[i];
        else if (i < n0 + n1)       v = w1[i - n0];
        else if (i < n0 + 2 * n1)   v = w2[i - n0 - n1];
        else return;
        __nv_bfloat16 h, l;
        split_bf16(v, h, l);
        g_wh[i] = h;
        g_wl[i] = l;
        return;
    }

    if (tid < COUT) {
        #pragma unroll
        for (int s = 0; s < 3; s++) { g_sum[s][tid] = 0.f; g_sum2[s][tid] = 0.f; }
    }
    for (int j = tid; j < 9 * 256; j += 256) {
        int k = j >> 8, c = j & 255;
        g_rot[j] = ro[c * 9 + k];
    }
}

// ---------------- 2) deformable gather — channel-last, LDG.128 ----------------
__global__ void __launch_bounds__(256)
gather_kernel(const float* __restrict__ xT, const float* __restrict__ rot) {
    __shared__ float4 s_tap[16 * 9];
    int px0 = blockIdx.x * 16;
    int tid = threadIdx.x;
    for (int i = tid; i < 144; i += 256)
        s_tap[i] = g_tap[px0 * 9 + i];
    __syncthreads();
    int lane = tid & 31, warp = tid >> 5;
    int c = (warp & 1) * 128 + lane * 4;
    int pg = warp >> 1;
    float4 rk[9];
    #pragma unroll
    for (int k = 0; k < 9; k++) rk[k] = *(const float4*)&rot[k * 256 + c];
    #pragma unroll
    for (int i = 0; i < 4; i++) {
        int pl = pg * 4 + i;
        int p = px0 + pl;
        float a0 = 0.f, a1 = 0.f, a2 = 0.f, a3 = 0.f;
        #pragma unroll
        for (int k = 0; k < 9; k++) {
            float4 rec = s_tap[pl * 9 + k];
            const float* rp = xT + (size_t)__float_as_int(rec.x) * 256 + c;
            float4 v0 = *(const float4*)rp;
            float4 v1 = *(const float4*)(rp + 256);
            float4 v2 = *(const float4*)(rp + 512);
            float s0 = fmaf(rec.y, v0.x, fmaf(rec.z, v1.x, rec.w * v2.x));
            float s1 = fmaf(rec.y, v0.y, fmaf(rec.z, v1.y, rec.w * v2.y));
            float s2 = fmaf(rec.y, v0.z, fmaf(rec.z, v1.z, rec.w * v2.z));
            float s3 = fmaf(rec.y, v0.w, fmaf(rec.z, v1.w, rec.w * v2.w));
            a0 = fmaf(rk[k].x, s0, a0);
            a1 = fmaf(rk[k].y, s1, a1);
            a2 = fmaf(rk[k].z, s2, a2);
            a3 = fmaf(rk[k].w, s3, a3);
        }
        __nv_bfloat16 h[4], l[4];
        split_bf16(a0, h[0], l[0]); split_bf16(a1, h[1], l[1]);
        split_bf16(a2, h[2], l[2]); split_bf16(a3, h[3], l[3]);
        *(uint2*)&g_y0h[(size_t)p * 256 + c] = *(uint2*)h;
        *(uint2*)&g_y0l[(size_t)p * 256 + c] = *(uint2*)l;
    }
}

// ---------------- 3) bf16 split tensor-core GEMM: cp.async + ldmatrix ----------
__device__ __forceinline__ void mma_bf16(float d[4], const uint32_t a[4], const uint32_t b0, const uint32_t b1) {
    asm volatile(
        "mma.sync.aligned.m16n8k16.row.col.f32.bf16.bf16.f32 "
        "{%0,%1,%2,%3}, {%4,%5,%6,%7}, {%8,%9}, {%10,%11,%12,%13};"
        : "=f"(d[0]), "=f"(d[1]), "=f"(d[2]), "=f"(d[3])
        : "r"(a[0]), "r"(a[1]), "r"(a[2]), "r"(a[3]),
          "r"(b0), "r"(b1),
          "f"(d[0]), "f"(d[1]), "f"(d[2]), "f"(d[3]));
}

#define CP8(dst, src) \
    asm volatile("cp.async.ca.shared.global [%0], [%1], 8;" :: "r"(dst), "l"(src))
#define LDSM_X4(r0, r1, r2, r3, addr) \
    asm volatile("ldmatrix.sync.aligned.m8n8.x4.shared.b16 {%0,%1,%2,%3}, [%4];" \
                 : "=r"(r0), "=r"(r1), "=r"(r2), "=r"(r3) : "r"(addr))
#define LDSM_X4T(r0, r1, r2, r3, addr) \
    asm volatile("ldmatrix.sync.aligned.m8n8.x4.trans.shared.b16 {%0,%1,%2,%3}, [%4];" \
                 : "=r"(r0), "=r"(r1), "=r"(r2), "=r"(r3) : "r"(addr))

template<bool BT>
__global__ void __launch_bounds__(256)
gemm_kernel(const __nv_bfloat16* __restrict__ Ahg,
            const __nv_bfloat16* __restrict__ Alg,
            const __nv_bfloat16* __restrict__ Bh,
            const __nv_bfloat16* __restrict__ Bl,
            float* __restrict__ C, int K,
            float* __restrict__ sum, float* __restrict__ sum2) {
    constexpr int BBY = BT ? 2048 : 3072;
    constexpr int BUFSZ = 6144 + 2 * BBY;
    __shared__ __align__(16) char sm[3 * BUFSZ];
    const int N = HW;
    int bn = blockIdx.x * 64, bm = blockIdx.y * 64;
    int tid = threadIdx.x;
    int lane = tid & 31;
    int warp = tid >> 5;
    int g = lane >> 2, t = lane & 3;
    int m0 = (warp & 1) * 32;
    int n0 = (warp >> 1) * 16;

    uint32_t smb = (uint32_t)__cvta_generic_to_shared(sm);

    int ar  = tid >> 2, akq = tid & 3;
    uint32_t aoffst = ar * 48 + akq * 8;
    const __nv_bfloat16* ApH = Ahg + (size_t)(bm + ar) * K + akq * 4;
    const __nv_bfloat16* ApL = Alg + (size_t)(bm + ar) * K + akq * 4;

    uint32_t boffst;
    const __nv_bfloat16 *BpH, *BpL;
    if (BT) {
        int bkr = tid >> 4, bn4 = (tid & 15) * 4;
        int bu = (tid & 15) >> 1, bhalf = tid & 1;
        boffst = bkr * 128 + (uint32_t)((bu ^ (bkr & 7)) << 4) + bhalf * 8;
        BpH = Bh + (size_t)bkr * N + bn + bn4;
        BpL = Bl + (size_t)bkr * N + bn + bn4;
    } else {
        boffst = aoffst;
        BpH = Bh + (size_t)(bn + ar) * K + akq * 4;
        BpL = Bl + (size_t)(bn + ar) * K + akq * 4;
    }

    uint32_t aoffld[2];
    #pragma unroll
    for (int mt = 0; mt < 2; mt++)
        aoffld[mt] = (uint32_t)((m0 + mt * 16 + (lane & 15)) * 48 + (lane >> 4) * 16);
    uint32_t boffld;
    if (BT) {
        int mi = lane >> 3;
        int kk = (mi & 1) * 8 + (lane & 7);
        int u  = (n0 >> 3) + (mi >> 1);
        boffld = (uint32_t)(kk * 128 + ((u ^ (kk & 7)) << 4));
    } else {
        boffld = (uint32_t)((n0 + (lane & 15)) * 48 + (lane >> 4) * 16);
    }

    float d[2][2][4];
    #pragma unroll
    for (int i = 0; i < 2; i++)
        #pragma unroll
        for (int j = 0; j < 2; j++)
            #pragma unroll
            for (int q = 0; q < 4; q++) d[i][j][q] = 0.f;

    int nstage = K / 16;

    #pragma unroll
    for (int s = 0; s < 2; s++) {
        uint32_t base = smb + s * BUFSZ;
        int k0 = s * 16;
        CP8(base + aoffst,        ApH + k0);
        CP8(base + 3072 + aoffst, ApL + k0);
        if (BT) {
            CP8(base + 6144 + boffst,       BpH + (size_t)k0 * N);
            CP8(base + 6144 + BBY + boffst, BpL + (size_t)k0 * N);
        } else {
            CP8(base + 6144 + boffst,       BpH + k0);
            CP8(base + 6144 + BBY + boffst, BpL + k0);
        }
        asm volatile("cp.async.commit_group;");
    }

    int bufc = 0;
    for (int s = 0; s < nstage; s++) {
        if (s + 1 < nstage) asm volatile("cp.async.wait_group 1;");
        else                asm volatile("cp.async.wait_group 0;");
        __syncthreads();

        if (s + 2 < nstage) {
            int nb = bufc + 2; if (nb >= 3) nb -= 3;
            uint32_t base = smb + nb * BUFSZ;
            int k0 = (s + 2) * 16;
            CP8(base + aoffst,        ApH + k0);
            CP8(base + 3072 + aoffst, ApL + k0);
            if (BT) {
                CP8(base + 6144 + boffst,       BpH + (size_t)k0 * N);
                CP8(base + 6144 + BBY + boffst, BpL + (size_t)k0 * N);
            } else {
                CP8(base + 6144 + boffst,       BpH + k0);
                CP8(base + 6144 + BBY + boffst, BpL + k0);
            }
            asm volatile("cp.async.commit_group;");
        }

        uint32_t base = smb + bufc * BUFSZ;
        uint32_t ah[2][4], al[2][4], bhf[4], blf[4];
        LDSM_X4(ah[0][0], ah[0][1], ah[0][2], ah[0][3], base + aoffld[0]);
        LDSM_X4(ah[1][0], ah[1][1], ah[1][2], ah[1][3], base + aoffld[1]);
        LDSM_X4(al[0][0], al[0][1], al[0][2], al[0][3], base + 3072 + aoffld[0]);
        LDSM_X4(al[1][0], al[1][1], al[1][2], al[1][3], base + 3072 + aoffld[1]);
        if (BT) {
            LDSM_X4T(bhf[0], bhf[1], bhf[2], bhf[3], base + 6144 + boffld);
            LDSM_X4T(blf[0], blf[1], blf[2], blf[3], base + 6144 + BBY + boffld);
        } else {
            LDSM_X4(bhf[0], bhf[1], bhf[2], bhf[3], base + 6144 + boffld);
            LDSM_X4(blf[0], blf[1], blf[2], blf[3], base + 6144 + BBY + boffld);
        }

        constexpr int i0 = BT ? 1 : 2;
        #pragma unroll
        for (int mt = 0; mt < 2; mt++) {
            mma_bf16(d[mt][0], ah[mt], bhf[0], bhf[i0]);
            mma_bf16(d[mt][0], ah[mt], blf[0], blf[i0]);
            mma_bf16(d[mt][0], al[mt], bhf[0], bhf[i0]);
            mma_bf16(d[mt][1], ah[mt], bhf[3 - i0], bhf[3]);
            mma_bf16(d[mt][1], ah[mt], blf[3 - i0], blf[3]);
            mma_bf16(d[mt][1], al[mt], bhf[3 - i0], bhf[3]);
        }

        if (++bufc == 3) bufc = 0;
    }

    float srow[2][2] = {{0.f, 0.f}, {0.f, 0.f}};
    float qrow[2][2] = {{0.f, 0.f}, {0.f, 0.f}};
    #pragma unroll
    for (int mt = 0; mt < 2; mt++) {
        int r0 = bm + m0 + mt * 16 + g;
        #pragma unroll
        for (int nt = 0; nt < 2; nt++) {
            int col = bn + n0 + nt * 8 + 2 * t;
            float2 v0 = make_float2(d[mt][nt][0], d[mt][nt][1]);
            float2 v1 = make_float2(d[mt][nt][2], d[mt][nt][3]);
            *(float2*)&C[(size_t)r0 * N + col] = v0;
            *(float2*)&C[(size_t)(r0 + 8) * N + col] = v1;
            srow[mt][0] += v0.x + v0.y;
            srow[mt][1] += v1.x + v1.y;
            qrow[mt][0] = fmaf(v0.x, v0.x, fmaf(v0.y, v0.y, qrow[mt][0]));
            qrow[mt][1] = fmaf(v1.x, v1.x, fmaf(v1.y, v1.y, qrow[mt][1]));
        }
    }
    #pragma unroll
    for (int mt = 0; mt < 2; mt++)
        #pragma unroll
        for (int h = 0; h < 2; h++) {
            float s = srow[mt][h], q = qrow[mt][h];
            s += __shfl_down_sync(0xffffffffu, s, 1, 4);
            s += __shfl_down_sync(0xffffffffu, s, 2, 4);
            q += __shfl_down_sync(0xffffffffu, q, 1, 4);
            q += __shfl_down_sync(0xffffffffu, q, 2, 4);
            if (t == 0) {
                int row = bm + m0 + mt * 16 + g + h * 8;
                atomicAdd(&sum[row], s);
                atomicAdd(&sum2[row], q);
            }
        }
}

// ---------------- BN scale/bias from accumulated stats ----------------
__device__ __forceinline__ void bn_coeffs(int c, const float* sum, const float* sum2,
                                          const float* __restrict__ g,
                                          const float* __restrict__ b,
                                          float& sc, float& bi) {
    float mean = sum[c] * (1.f / (float)HW);
    float var  = sum2[c] * (1.f / (float)HW) - mean * mean;
    float rstd = rsqrtf(var + EPSv);
    sc = g[c] * rstd;
    bi = b[c] - mean * sc;
}

__device__ __forceinline__ float bn_leaky(float v, float sc, float bi) {
    float y = fmaf(v, sc, bi);
    return y >= 0.f ? y : LEAK * y;
}

// ---------------- 4) depthwise 3x3, 4 px/thread, interior fast path ----------------
__global__ void dw_kernel(const float* __restrict__ in, const float* __restrict__ dw,
                          __nv_bfloat16* __restrict__ outh, __nv_bfloat16* __restrict__ outl,
                          const float* __restrict__ sum, const float* __restrict__ sum2,
                          const float* __restrict__ g, const float* __restrict__ b) {
    int c = blockIdx.y;
    int q = blockIdx.x * 256 + threadIdx.x;
    if (q >= HW / 4) return;
    int p0 = q * 4;
    int r = p0 / Ww, col0 = p0 - r * Ww;
    float sc, bi;
    bn_coeffs(c, sum, sum2, g, b, sc, bi);
    float wl[9];
    #pragma unroll
    for (int i = 0; i < 9; i++) wl[i] = dw[c * 9 + i];
    const float* ip = in + (size_t)c * HW;
    float vin[3][6];

    bool interior = (r >= 1) & (r <= Hh - 2) & (col0 >= 4) & (col0 <= Ww - 8);
    if (interior) {
        // no predicates: per row one aligned float4 + 2 scalars
        #pragma unroll
        for (int tr = 0; tr < 3; tr++) {
            const float* rp = ip + (r + tr - 1) * Ww + col0;
            float4 mid = *(const float4*)rp;
            vin[tr][0] = bn_leaky(rp[-1],  sc, bi);
            vin[tr][1] = bn_leaky(mid.x,   sc, bi);
            vin[tr][2] = bn_leaky(mid.y,   sc, bi);
            vin[tr][3] = bn_leaky(mid.z,   sc, bi);
            vin[tr][4] = bn_leaky(mid.w,   sc, bi);
            vin[tr][5] = bn_leaky(rp[4],   sc, bi);
        }
    } else {
        #pragma unroll
        for (int tr = 0; tr < 3; tr++) {
            int rr = r + tr - 1;
            bool rowok = (rr >= 0 && rr < Hh);
            #pragma unroll
            for (int j = 0; j < 6; j++) {
                int cc = col0 - 1 + j;
                float v = 0.f;
                if (rowok && cc >= 0 && cc < Ww)
                    v = bn_leaky(ip[rr * Ww + cc], sc, bi);
                vin[tr][j] = v;
            }
        }
    }
    __nv_bfloat16 oh[4], ol[4];
    #pragma unroll
    for (int i = 0; i < 4; i++) {
        float acc = 0.f;
        #pragma unroll
        for (int tr = 0; tr < 3; tr++)
            #pragma unroll
            for (int dx = 0; dx < 3; dx++)
                acc = fmaf(vin[tr][i + dx], wl[tr * 3 + dx], acc);
        split_bf16(acc, oh[i], ol[i]);
    }
    *(uint2*)&outh[(size_t)c * HW + p0] = *(uint2*)oh;
    *(uint2*)&outl[(size_t)c * HW + p0] = *(uint2*)ol;
}

// ---------------- 5) final BN+leaky apply (vectorized) ----------------
__global__ void apply_kernel(const float* __restrict__ in, float* __restrict__ out,
                             const float* __restrict__ sum, const float* __restrict__ sum2,
                             const float* __restrict__ g, const float* __restrict__ b) {
    int i = blockIdx.x * 256 + threadIdx.x;
    if (i >= COUT * HW / 4) return;
    int c = (i * 4) / HW;
    float sc, bi;
    bn_coeffs(c, sum, sum2, g, b, sc, bi);
    float4 v = ((const float4*)in)[i];
    v.x = bn_leaky(v.x, sc, bi);
    v.y = bn_leaky(v.y, sc, bi);
    v.z = bn_leaky(v.z, sc, bi);
    v.w = bn_leaky(v.w, sc, bi);
    ((float4*)out)[i] = v;
}

// ---------------- launch ----------------
extern "C" void kernel_launch(void* const* d_in, const int* in_sizes, int n_in,
                              void* d_out, int out_size) {
    const float* x        = (const float*)d_in[0];
    const float* x_range  = (const float*)d_in[1];
    const float* range_o  = (const float*)d_in[2];
    const float* w_reduce = (const float*)d_in[3];
    const float* g_r      = (const float*)d_in[4];
    const float* b_r      = (const float*)d_in[5];
    const float* dw1      = (const float*)d_in[6];
    const float* pw1      = (const float*)d_in[7];
    const float* g1       = (const float*)d_in[8];
    const float* b1       = (const float*)d_in[9];
    const float* dw2      = (const float*)d_in[10];
    const float* pw2      = (const float*)d_in[11];
    const float* g2       = (const float*)d_in[12];
    const float* b2       = (const float*)d_in[13];
    float* out = (float*)d_out;

    float *t1, *t3, *xT, *rot, *sumb, *sum2b;
    __nv_bfloat16 *y0h, *y0l, *t2h, *t2l, *wh, *wlp;
    cudaGetSymbolAddress((void**)&t1, g_t1);
    cudaGetSymbolAddress((void**)&t3, g_t3);
    cudaGetSymbolAddress((void**)&xT, g_xT);
    cudaGetSymbolAddress((void**)&rot, g_rot);
    cudaGetSymbolAddress((void**)&y0h, g_y0h);
    cudaGetSymbolAddress((void**)&y0l, g_y0l);
    cudaGetSymbolAddress((void**)&t2h, g_t2h);
    cudaGetSymbolAddress((void**)&t2l, g_t2l);
    cudaGetSymbolAddress((void**)&wh, g_wh);
    cudaGetSymbolAddress((void**)&wlp, g_wl);
    cudaGetSymbolAddress((void**)&sumb, g_sum);
    cudaGetSymbolAddress((void**)&sum2b, g_sum2);
    float* s0  = sumb;            float* q0 = sum2b;
    float* s1  = sumb + COUT;     float* q1 = sum2b + COUT;
    float* s2  = sumb + 2*COUT;   float* q2 = sum2b + 2*COUT;
    const int W0 = COUT * CIN;
    const int W1 = COUT * COUT;

    prep_kernel<<<1073, 256>>>(x, x_range, range_o, w_reduce, pw1, pw2);
    gather_kernel<<<HW / 16, 256>>>(xT, rot);

    gemm_kernel<false><<<dim3(HW / 64, COUT / 64), 256>>>(wh, wlp, y0h, y0l, t1, CIN, s0, q0);
    dw_kernel<<<dim3(HW / 4 / 256, COUT), 256>>>(t1, dw1, t2h, t2l, s0, q0, g_r, b_r);

    gemm_kernel<true><<<dim3(HW / 64, COUT / 64), 256>>>(wh + W0, wlp + W0, t2h, t2l, t3, COUT, s1, q1);
    dw_kernel<<<dim3(HW / 4 / 256, COUT), 256>>>(t3, dw2, t2h, t2l, s1, q1, g1, b1);

    gemm_kernel<true><<<dim3(HW / 64, COUT / 64), 256>>>(wh + W0 + W1, wlp + W0 + W1, t2h, t2l, t1, COUT, s2, q2);
    apply_kernel<<<(COUT * HW / 4 + 255) / 256, 256>>>(t1, out, s2, q2, g2, b2);
}

// round 14
// speedup vs baseline: 1.0632x; 1.0632x over previous
#include <cuda_runtime.h>
#include <cuda_bf16.h>
#include <math.h>
#include <stdint.h>

// Problem constants
#define CIN   256
#define COUT  128
#define Hh    64
#define Ww    192
#define HW    (Hh*Ww)          // 12288
#define Hp    (Hh+2)           // 66
#define Wp    (Ww+2)           // 194
#define Pp    (Hp*Wp)          // 12804
#define EPSv  1e-5f
#define LEAK  0.01f

// ---------------- scratch (static __device__ — no allocation) ----------------
__device__ float4 g_tap[HW * 9];            // packed {base(int), w0, w1, w2} per (px,tap)
__device__ float g_xT[HW * CIN];            // x transposed to [p][c]  (12.6 MB)
__device__ float g_rot[9 * 256];            // ro transposed to [k][c]
__device__ __nv_bfloat16 g_y0h[HW * CIN];   // gather out, PIXEL-major [p][c], hi
__device__ __nv_bfloat16 g_y0l[HW * CIN];   // lo
__device__ float g_t1[COUT * HW];           // GEMM fp32 outputs [c][p]
__device__ float g_t3[COUT * HW];
__device__ __nv_bfloat16 g_t2h[COUT * HW];  // dw output hi/lo planes [c][p]
__device__ __nv_bfloat16 g_t2l[COUT * HW];
__device__ __nv_bfloat16 g_wh[COUT * (CIN + COUT + COUT)];  // pre-split weights hi
__device__ __nv_bfloat16 g_wl[COUT * (CIN + COUT + COUT)];  // lo
__device__ float g_sum[3][COUT];
__device__ float g_sum2[3][COUT];

__device__ __forceinline__ void split_bf16(float v, __nv_bfloat16& h, __nv_bfloat16& l) {
    h = __float2bfloat16(v);
    l = __float2bfloat16(v - __bfloat162float(h));
}

// =================== 1) fused prep kernel ===================
// blocks [0,768)       : x transpose, 64px x 64ch float4 tiles
// blocks [768,816)     : gather tables (48 blocks x 256 px)
// blocks [816,1072)    : weight split (256 blocks x 256 elems)
// block  1072          : stat zero + ro transpose
__global__ void __launch_bounds__(256)
prep_kernel(const float* __restrict__ x, const float* __restrict__ xr,
            const float* __restrict__ ro,
            const float* __restrict__ w0, const float* __restrict__ w1,
            const float* __restrict__ w2) {
    int bid = blockIdx.x;
    int tid = threadIdx.x;

    if (bid < 768) {
        __shared__ float tile[64][65];
        int pb = (bid % 192) * 64, cb = (bid / 192) * 64;
        int tx = tid & 15, ty = tid >> 4;
        #pragma unroll
        for (int j = 0; j < 4; j++) {
            int cl = ty + 16 * j;
            float4 v = *(const float4*)&x[(size_t)(cb + cl) * HW + pb + tx * 4];
            tile[cl][tx * 4 + 0] = v.x;
            tile[cl][tx * 4 + 1] = v.y;
            tile[cl][tx * 4 + 2] = v.z;
            tile[cl][tx * 4 + 3] = v.w;
        }
        __syncthreads();
        #pragma unroll
        for (int j = 0; j < 4; j++) {
            int pl = ty + 16 * j;
            int cl = tx * 4;
            float4 v = make_float4(tile[cl][pl], tile[cl + 1][pl],
                                   tile[cl + 2][pl], tile[cl + 3][pl]);
            *(float4*)&g_xT[(size_t)(pb + pl) * 256 + cb + cl] = v;
        }
        return;
    }

    if (bid < 816) {
        int p = (bid - 768) * 256 + tid;
        if (p >= HW) return;
        float off = 3.0f * (1.0f / (1.0f + expf(-xr[p])));
        int r = p / Ww, cc = p - r * Ww;
        float v0 = (float)((r + 1) * Wp + (cc + 1));
        const float xo9[9] = {-1,0,1,-1,0,1,-1,0,1};
        const float yo9[9] = {-1,-1,-1,0,0,0,1,1,1};
        const float Pm1 = (float)(Pp - 1);
        const float Wpf = (float)Wp;
        #pragma unroll
        for (int k = 0; k < 9; k++) {
            float xo = xo9[k], yo = yo9[k];
            float pre  = v0 + xo + yo * Wpf;
            float offv = __fadd_rn(__fmul_rn(off, xo), yo * Wpf);
            float after = __fadd_rn(pre, offv);
            float avf  = fminf(fmaxf(pre + floorf(offv), 0.f), Pm1);
            float avf1 = fminf(fmaxf(avf + xo, 0.f), Pm1);
            float avc  = fminf(fmaxf(pre + ceilf(offv), 0.f), Pm1);
            float avc1 = fminf(fmaxf(avc + xo, 0.f), Pm1);
            float g1w = fabsf((after - avf)  / Wpf);
            float g2w = fabsf((avc1 - after) / Wpf);
            float wq[4];
            wq[0] = g1w * fabsf(after - avf);
            wq[1] = g1w * fabsf(avf1 - after);
            wq[2] = g2w * fabsf(after - avc1);
            wq[3] = g2w * fabsf(avc  - after);
            int iq[4] = {(int)avf, (int)avf1, (int)avc1, (int)avc};
            int lo = min(min(iq[0], iq[1]), min(iq[2], iq[3]));
            float w3[3] = {0.f, 0.f, 0.f};
            #pragma unroll
            for (int j = 0; j < 4; j++) w3[iq[j] - lo] += wq[j];
            int vbase = -1, firstslot = 0;
            #pragma unroll
            for (int s = 0; s < 3; s++) {
                int id = lo + s;
                int rr = id / Wp, c2 = id - rr * Wp;
                bool valid = (rr >= 1 && rr <= Hh && c2 >= 1 && c2 <= Ww);
                if (!valid) w3[s] = 0.f;
                else if (w3[s] != 0.f && vbase < 0) {
                    vbase = (rr - 1) * Ww + (c2 - 1);
                    firstslot = s;
                }
            }
            float fw[3] = {0.f, 0.f, 0.f};
            int bidx = 0;
            if (vbase >= 0) {
                int base = vbase - firstslot;
                bidx = min(max(base, 0), HW - 3);
                #pragma unroll
                for (int s = 0; s < 3; s++)
                    if (w3[s] != 0.f) fw[(base + s) - bidx] += w3[s];
            }
            g_tap[p * 9 + k] = make_float4(__int_as_float(bidx), fw[0], fw[1], fw[2]);
        }
        return;
    }

    if (bid < 1072) {
        int i = (bid - 816) * 256 + tid;
        const int n0 = COUT * CIN;
        const int n1 = COUT * COUT;
        float v;
        if (i < n0)                 v = w0[i];
        else if (i < n0 + n1)       v = w1[i - n0];
        else if (i < n0 + 2 * n1)   v = w2[i - n0 - n1];
        else return;
        __nv_bfloat16 h, l;
        split_bf16(v, h, l);
        g_wh[i] = h;
        g_wl[i] = l;
        return;
    }

    if (tid < COUT) {
        #pragma unroll
        for (int s = 0; s < 3; s++) { g_sum[s][tid] = 0.f; g_sum2[s][tid] = 0.f; }
    }
    for (int j = tid; j < 9 * 256; j += 256) {
        int k = j >> 8, c = j & 255;
        g_rot[j] = ro[c * 9 + k];
    }
}

// ---------------- 2) deformable gather — channel-last, LDG.128 ----------------
__global__ void __launch_bounds__(256)
gather_kernel(const float* __restrict__ xT, const float* __restrict__ rot) {
    __shared__ float4 s_tap[16 * 9];
    int px0 = blockIdx.x * 16;
    int tid = threadIdx.x;
    for (int i = tid; i < 144; i += 256)
        s_tap[i] = g_tap[px0 * 9 + i];
    __syncthreads();
    int lane = tid & 31, warp = tid >> 5;
    int c = (warp & 1) * 128 + lane * 4;
    int pg = warp >> 1;
    float4 rk[9];
    #pragma unroll
    for (int k = 0; k < 9; k++) rk[k] = *(const float4*)&rot[k * 256 + c];
    #pragma unroll
    for (int i = 0; i < 4; i++) {
        int pl = pg * 4 + i;
        int p = px0 + pl;
        float a0 = 0.f, a1 = 0.f, a2 = 0.f, a3 = 0.f;
        #pragma unroll
        for (int k = 0; k < 9; k++) {
            float4 rec = s_tap[pl * 9 + k];
            const float* rp = xT + (size_t)__float_as_int(rec.x) * 256 + c;
            float4 v0 = *(const float4*)rp;
            float4 v1 = *(const float4*)(rp + 256);
            float4 v2 = *(const float4*)(rp + 512);
            float s0 = fmaf(rec.y, v0.x, fmaf(rec.z, v1.x, rec.w * v2.x));
            float s1 = fmaf(rec.y, v0.y, fmaf(rec.z, v1.y, rec.w * v2.y));
            float s2 = fmaf(rec.y, v0.z, fmaf(rec.z, v1.z, rec.w * v2.z));
            float s3 = fmaf(rec.y, v0.w, fmaf(rec.z, v1.w, rec.w * v2.w));
            a0 = fmaf(rk[k].x, s0, a0);
            a1 = fmaf(rk[k].y, s1, a1);
            a2 = fmaf(rk[k].z, s2, a2);
            a3 = fmaf(rk[k].w, s3, a3);
        }
        __nv_bfloat16 h[4], l[4];
        split_bf16(a0, h[0], l[0]); split_bf16(a1, h[1], l[1]);
        split_bf16(a2, h[2], l[2]); split_bf16(a3, h[3], l[3]);
        *(uint2*)&g_y0h[(size_t)p * 256 + c] = *(uint2*)h;
        *(uint2*)&g_y0l[(size_t)p * 256 + c] = *(uint2*)l;
    }
}

// ---------------- 3) bf16 split tensor-core GEMM: cp.async + ldmatrix ----------
__device__ __forceinline__ void mma_bf16(float d[4], const uint32_t a[4], const uint32_t b0, const uint32_t b1) {
    asm volatile(
        "mma.sync.aligned.m16n8k16.row.col.f32.bf16.bf16.f32 "
        "{%0,%1,%2,%3}, {%4,%5,%6,%7}, {%8,%9}, {%10,%11,%12,%13};"
        : "=f"(d[0]), "=f"(d[1]), "=f"(d[2]), "=f"(d[3])
        : "r"(a[0]), "r"(a[1]), "r"(a[2]), "r"(a[3]),
          "r"(b0), "r"(b1),
          "f"(d[0]), "f"(d[1]), "f"(d[2]), "f"(d[3]));
}

#define CP8(dst, src) \
    asm volatile("cp.async.ca.shared.global [%0], [%1], 8;" :: "r"(dst), "l"(src))
#define LDSM_X4(r0, r1, r2, r3, addr) \
    asm volatile("ldmatrix.sync.aligned.m8n8.x4.shared.b16 {%0,%1,%2,%3}, [%4];" \
                 : "=r"(r0), "=r"(r1), "=r"(r2), "=r"(r3) : "r"(addr))
#define LDSM_X4T(r0, r1, r2, r3, addr) \
    asm volatile("ldmatrix.sync.aligned.m8n8.x4.trans.shared.b16 {%0,%1,%2,%3}, [%4];" \
                 : "=r"(r0), "=r"(r1), "=r"(r2), "=r"(r3) : "r"(addr))

template<bool BT>
__global__ void __launch_bounds__(256)
gemm_kernel(const __nv_bfloat16* __restrict__ Ahg,
            const __nv_bfloat16* __restrict__ Alg,
            const __nv_bfloat16* __restrict__ Bh,
            const __nv_bfloat16* __restrict__ Bl,
            float* __restrict__ C, int K,
            float* __restrict__ sum, float* __restrict__ sum2) {
    constexpr int BBY = BT ? 2048 : 3072;
    constexpr int BUFSZ = 6144 + 2 * BBY;
    __shared__ __align__(16) char sm[3 * BUFSZ];
    const int N = HW;
    int bn = blockIdx.x * 64, bm = blockIdx.y * 64;
    int tid = threadIdx.x;
    int lane = tid & 31;
    int warp = tid >> 5;
    int g = lane >> 2, t = lane & 3;
    int m0 = (warp & 1) * 32;
    int n0 = (warp >> 1) * 16;

    uint32_t smb = (uint32_t)__cvta_generic_to_shared(sm);

    int ar  = tid >> 2, akq = tid & 3;
    uint32_t aoffst = ar * 48 + akq * 8;
    const __nv_bfloat16* ApH = Ahg + (size_t)(bm + ar) * K + akq * 4;
    const __nv_bfloat16* ApL = Alg + (size_t)(bm + ar) * K + akq * 4;

    uint32_t boffst;
    const __nv_bfloat16 *BpH, *BpL;
    if (BT) {
        int bkr = tid >> 4, bn4 = (tid & 15) * 4;
        int bu = (tid & 15) >> 1, bhalf = tid & 1;
        boffst = bkr * 128 + (uint32_t)((bu ^ (bkr & 7)) << 4) + bhalf * 8;
        BpH = Bh + (size_t)bkr * N + bn + bn4;
        BpL = Bl + (size_t)bkr * N + bn + bn4;
    } else {
        boffst = aoffst;
        BpH = Bh + (size_t)(bn + ar) * K + akq * 4;
        BpL = Bl + (size_t)(bn + ar) * K + akq * 4;
    }

    uint32_t aoffld[2];
    #pragma unroll
    for (int mt = 0; mt < 2; mt++)
        aoffld[mt] = (uint32_t)((m0 + mt * 16 + (lane & 15)) * 48 + (lane >> 4) * 16);
    uint32_t boffld;
    if (BT) {
        int mi = lane >> 3;
        int kk = (mi & 1) * 8 + (lane & 7);
        int u  = (n0 >> 3) + (mi >> 1);
        boffld = (uint32_t)(kk * 128 + ((u ^ (kk & 7)) << 4));
    } else {
        boffld = (uint32_t)((n0 + (lane & 15)) * 48 + (lane >> 4) * 16);
    }

    float d[2][2][4];
    #pragma unroll
    for (int i = 0; i < 2; i++)
        #pragma unroll
        for (int j = 0; j < 2; j++)
            #pragma unroll
            for (int q = 0; q < 4; q++) d[i][j][q] = 0.f;

    int nstage = K / 16;

    #pragma unroll
    for (int s = 0; s < 2; s++) {
        uint32_t base = smb + s * BUFSZ;
        int k0 = s * 16;
        CP8(base + aoffst,        ApH + k0);
        CP8(base + 3072 + aoffst, ApL + k0);
        if (BT) {
            CP8(base + 6144 + boffst,       BpH + (size_t)k0 * N);
            CP8(base + 6144 + BBY + boffst, BpL + (size_t)k0 * N);
        } else {
            CP8(base + 6144 + boffst,       BpH + k0);
            CP8(base + 6144 + BBY + boffst, BpL + k0);
        }
        asm volatile("cp.async.commit_group;");
    }

    int bufc = 0;
    for (int s = 0; s < nstage; s++) {
        if (s + 1 < nstage) asm volatile("cp.async.wait_group 1;");
        else                asm volatile("cp.async.wait_group 0;");
        __syncthreads();

        if (s + 2 < nstage) {
            int nb = bufc + 2; if (nb >= 3) nb -= 3;
            uint32_t base = smb + nb * BUFSZ;
            int k0 = (s + 2) * 16;
            CP8(base + aoffst,        ApH + k0);
            CP8(base + 3072 + aoffst, ApL + k0);
            if (BT) {
                CP8(base + 6144 + boffst,       BpH + (size_t)k0 * N);
                CP8(base + 6144 + BBY + boffst, BpL + (size_t)k0 * N);
            } else {
                CP8(base + 6144 + boffst,       BpH + k0);
                CP8(base + 6144 + BBY + boffst, BpL + k0);
            }
            asm volatile("cp.async.commit_group;");
        }

        uint32_t base = smb + bufc * BUFSZ;
        uint32_t ah[2][4], al[2][4], bhf[4], blf[4];
        LDSM_X4(ah[0][0], ah[0][1], ah[0][2], ah[0][3], base + aoffld[0]);
        LDSM_X4(ah[1][0], ah[1][1], ah[1][2], ah[1][3], base + aoffld[1]);
        LDSM_X4(al[0][0], al[0][1], al[0][2], al[0][3], base + 3072 + aoffld[0]);
        LDSM_X4(al[1][0], al[1][1], al[1][2], al[1][3], base + 3072 + aoffld[1]);
        if (BT) {
            LDSM_X4T(bhf[0], bhf[1], bhf[2], bhf[3], base + 6144 + boffld);
            LDSM_X4T(blf[0], blf[1], blf[2], blf[3], base + 6144 + BBY + boffld);
        } else {
            LDSM_X4(bhf[0], bhf[1], bhf[2], bhf[3], base + 6144 + boffld);
            LDSM_X4(blf[0], blf[1], blf[2], blf[3], base + 6144 + BBY + boffld);
        }

        constexpr int i0 = BT ? 1 : 2;
        #pragma unroll
        for (int mt = 0; mt < 2; mt++) {
            mma_bf16(d[mt][0], ah[mt], bhf[0], bhf[i0]);
            mma_bf16(d[mt][0], ah[mt], blf[0], blf[i0]);
            mma_bf16(d[mt][0], al[mt], bhf[0], bhf[i0]);
            mma_bf16(d[mt][1], ah[mt], bhf[3 - i0], bhf[3]);
            mma_bf16(d[mt][1], ah[mt], blf[3 - i0], blf[3]);
            mma_bf16(d[mt][1], al[mt], bhf[3 - i0], bhf[3]);
        }

        if (++bufc == 3) bufc = 0;
    }

    float srow[2][2] = {{0.f, 0.f}, {0.f, 0.f}};
    float qrow[2][2] = {{0.f, 0.f}, {0.f, 0.f}};
    #pragma unroll
    for (int mt = 0; mt < 2; mt++) {
        int r0 = bm + m0 + mt * 16 + g;
        #pragma unroll
        for (int nt = 0; nt < 2; nt++) {
            int col = bn + n0 + nt * 8 + 2 * t;
            float2 v0 = make_float2(d[mt][nt][0], d[mt][nt][1]);
            float2 v1 = make_float2(d[mt][nt][2], d[mt][nt][3]);
            *(float2*)&C[(size_t)r0 * N + col] = v0;
            *(float2*)&C[(size_t)(r0 + 8) * N + col] = v1;
            srow[mt][0] += v0.x + v0.y;
            srow[mt][1] += v1.x + v1.y;
            qrow[mt][0] = fmaf(v0.x, v0.x, fmaf(v0.y, v0.y, qrow[mt][0]));
            qrow[mt][1] = fmaf(v1.x, v1.x, fmaf(v1.y, v1.y, qrow[mt][1]));
        }
    }
    #pragma unroll
    for (int mt = 0; mt < 2; mt++)
        #pragma unroll
        for (int h = 0; h < 2; h++) {
            float s = srow[mt][h], q = qrow[mt][h];
            s += __shfl_down_sync(0xffffffffu, s, 1, 4);
            s += __shfl_down_sync(0xffffffffu, s, 2, 4);
            q += __shfl_down_sync(0xffffffffu, q, 1, 4);
            q += __shfl_down_sync(0xffffffffu, q, 2, 4);
            if (t == 0) {
                int row = bm + m0 + mt * 16 + g + h * 8;
                atomicAdd(&sum[row], s);
                atomicAdd(&sum2[row], q);
            }
        }
}

// ---------------- BN scale/bias from accumulated stats ----------------
__device__ __forceinline__ void bn_coeffs(int c, const float* sum, const float* sum2,
                                          const float* __restrict__ g,
                                          const float* __restrict__ b,
                                          float& sc, float& bi) {
    float mean = sum[c] * (1.f / (float)HW);
    float var  = sum2[c] * (1.f / (float)HW) - mean * mean;
    float rstd = rsqrtf(var + EPSv);
    sc = g[c] * rstd;
    bi = b[c] - mean * sc;
}

__device__ __forceinline__ float bn_leaky(float v, float sc, float bi) {
    float y = fmaf(v, sc, bi);
    return y >= 0.f ? y : LEAK * y;
}

// ---------------- 4) depthwise 3x3, 4x4 tile/thread, fused BN+leaky ----------------
// Loads 6x6 window once (36 predicated loads+bn) for 16 outputs.
__global__ void dw_kernel(const float* __restrict__ in, const float* __restrict__ dw,
                          __nv_bfloat16* __restrict__ outh, __nv_bfloat16* __restrict__ outl,
                          const float* __restrict__ sum, const float* __restrict__ sum2,
                          const float* __restrict__ g, const float* __restrict__ b) {
    const int TPC = (Hh / 4) * (Ww / 4);          // tiles per channel = 768
    int c = blockIdx.y;
    int q = blockIdx.x * 256 + threadIdx.x;
    if (q >= TPC) return;
    int rg = q / (Ww / 4), cg = q - rg * (Ww / 4);
    int r0 = rg * 4, col0 = cg * 4;
    float sc, bi;
    bn_coeffs(c, sum, sum2, g, b, sc, bi);
    float wl[9];
    #pragma unroll
    for (int i = 0; i < 9; i++) wl[i] = dw[c * 9 + i];
    const float* ip = in + (size_t)c * HW;

    float win[6][6];
    #pragma unroll
    for (int tr = 0; tr < 6; tr++) {
        int rr = r0 + tr - 1;
        bool rowok = (rr >= 0 && rr < Hh);
        #pragma unroll
        for (int j = 0; j < 6; j++) {
            int cc = col0 - 1 + j;
            float v = 0.f;
            if (rowok && cc >= 0 && cc < Ww)
                v = bn_leaky(ip[rr * Ww + cc], sc, bi);
            win[tr][j] = v;
        }
    }
    #pragma unroll
    for (int i = 0; i < 4; i++) {
        __nv_bfloat16 oh[4], ol[4];
        #pragma unroll
        for (int k = 0; k < 4; k++) {
            float acc = 0.f;
            #pragma unroll
            for (int tr = 0; tr < 3; tr++)
                #pragma unroll
                for (int dx = 0; dx < 3; dx++)
                    acc = fmaf(win[i + tr][k + dx], wl[tr * 3 + dx], acc);
            split_bf16(acc, oh[k], ol[k]);
        }
        size_t o = (size_t)c * HW + (r0 + i) * Ww + col0;
        *(uint2*)&outh[o] = *(uint2*)oh;
        *(uint2*)&outl[o] = *(uint2*)ol;
    }
}

// ---------------- 5) final BN+leaky apply (vectorized) ----------------
__global__ void apply_kernel(const float* __restrict__ in, float* __restrict__ out,
                             const float* __restrict__ sum, const float* __restrict__ sum2,
                             const float* __restrict__ g, const float* __restrict__ b) {
    int i = blockIdx.x * 256 + threadIdx.x;
    if (i >= COUT * HW / 4) return;
    int c = (i * 4) / HW;
    float sc, bi;
    bn_coeffs(c, sum, sum2, g, b, sc, bi);
    float4 v = ((const float4*)in)[i];
    v.x = bn_leaky(v.x, sc, bi);
    v.y = bn_leaky(v.y, sc, bi);
    v.z = bn_leaky(v.z, sc, bi);
    v.w = bn_leaky(v.w, sc, bi);
    ((float4*)out)[i] = v;
}

// ---------------- launch ----------------
extern "C" void kernel_launch(void* const* d_in, const int* in_sizes, int n_in,
                              void* d_out, int out_size) {
    const float* x        = (const float*)d_in[0];
    const float* x_range  = (const float*)d_in[1];
    const float* range_o  = (const float*)d_in[2];
    const float* w_reduce = (const float*)d_in[3];
    const float* g_r      = (const float*)d_in[4];
    const float* b_r      = (const float*)d_in[5];
    const float* dw1      = (const float*)d_in[6];
    const float* pw1      = (const float*)d_in[7];
    const float* g1       = (const float*)d_in[8];
    const float* b1       = (const float*)d_in[9];
    const float* dw2      = (const float*)d_in[10];
    const float* pw2      = (const float*)d_in[11];
    const float* g2       = (const float*)d_in[12];
    const float* b2       = (const float*)d_in[13];
    float* out = (float*)d_out;

    float *t1, *t3, *xT, *rot, *sumb, *sum2b;
    __nv_bfloat16 *y0h, *y0l, *t2h, *t2l, *wh, *wlp;
    cudaGetSymbolAddress((void**)&t1, g_t1);
    cudaGetSymbolAddress((void**)&t3, g_t3);
    cudaGetSymbolAddress((void**)&xT, g_xT);
    cudaGetSymbolAddress((void**)&rot, g_rot);
    cudaGetSymbolAddress((void**)&y0h, g_y0h);
    cudaGetSymbolAddress((void**)&y0l, g_y0l);
    cudaGetSymbolAddress((void**)&t2h, g_t2h);
    cudaGetSymbolAddress((void**)&t2l, g_t2l);
    cudaGetSymbolAddress((void**)&wh, g_wh);
    cudaGetSymbolAddress((void**)&wlp, g_wl);
    cudaGetSymbolAddress((void**)&sumb, g_sum);
    cudaGetSymbolAddress((void**)&sum2b, g_sum2);
    float* s0  = sumb;            float* q0 = sum2b;
    float* s1  = sumb + COUT;     float* q1 = sum2b + COUT;
    float* s2  = sumb + 2*COUT;   float* q2 = sum2b + 2*COUT;
    const int W0 = COUT * CIN;
    const int W1 = COUT * COUT;

    prep_kernel<<<1073, 256>>>(x, x_range, range_o, w_reduce, pw1, pw2);
    gather_kernel<<<HW / 16, 256>>>(xT, rot);

    gemm_kernel<false><<<dim3(HW / 64, COUT / 64), 256>>>(wh, wlp, y0h, y0l, t1, CIN, s0, q0);
    dw_kernel<<<dim3(3, COUT), 256>>>(t1, dw1, t2h, t2l, s0, q0, g_r, b_r);

    gemm_kernel<true><<<dim3(HW / 64, COUT / 64), 256>>>(wh + W0, wlp + W0, t2h, t2l, t3, COUT, s1, q1);
    dw_kernel<<<dim3(3, COUT), 256>>>(t3, dw2, t2h, t2l, s1, q1, g1, b1);

    gemm_kernel<true><<<dim3(HW / 64, COUT / 64), 256>>>(wh + W0 + W1, wlp + W0 + W1, t2h, t2l, t1, COUT, s2, q2);
    apply_kernel<<<(COUT * HW / 4 + 255) / 256, 256>>>(t1, out, s2, q2, g2, b2);
}